// round 13
// baseline (speedup 1.0000x reference)
#include <cuda_runtime.h>
#include <cuda_bf16.h>
#include <math.h>

#define NA 8400
#define BSZ 32
#define NM 32
#define NC 80
#define TOPK 9
#define CAPW 64
#define AG 64          // anchors per k_assign block
#define FINF 3.402823e38f

__device__ unsigned int g_maskpos[BSZ * NA];
__device__ float2       g_ac[NA];               // anchor centers

// Zero gt bitmask, compute anchor centers.
__global__ __launch_bounds__(256) void k_prep(const float* __restrict__ anc)
{
    const int i = blockIdx.x * blockDim.x + threadIdx.x;
    if (i < BSZ * NA / 4) ((uint4*)g_maskpos)[i] = make_uint4(0u, 0u, 0u, 0u);
    if (i < NA) {
        const float4 ab = ((const float4*)anc)[i];
        g_ac[i] = make_float2((ab.x + ab.z) * 0.5f, (ab.y + ab.w) * 0.5f);
    }
}

// One BLOCK (256 thr = 8 warps) per (b,g) pair; per-warp slice = L/8.
// Two-pass top-9 per (warp,level): pass1 = per-lane min(d2) over the slice;
// T = 9th-smallest lane-min via smem rank-select (slice superset bound);
// pass2 = push keys <= T via rare smem atomics; per-warp rank-select top-9;
// warp0 merges 72 keys per level and runs the threshold/atomicOr tail.
__global__ __launch_bounds__(256, 6) void k_pairs(
    const float* __restrict__ anc,
    const float* __restrict__ gtb,
    const float* __restrict__ mask_gt)
{
    __shared__ unsigned long long s_keys[3][72];
    __shared__ unsigned long long s_buf[8][CAPW];
    __shared__ float s_min[8][32];
    __shared__ int   s_cnt[8];
    __shared__ int   s_cand[27];

    const int tid  = threadIdx.x;
    const int lane = tid & 31;
    const int w    = tid >> 5;                  // 0..7

    const int p = blockIdx.x;
    const int b = p >> 5;
    const int g = p & 31;
    if (mask_gt[p] <= 0.0f) return;             // block-uniform -> barriers safe

    const float4 gt = ((const float4*)gtb)[p];
    const float gx = (gt.x + gt.z) * 0.5f;
    const float gy = (gt.y + gt.w) * 0.5f;

    const int starts[3] = {0, 6400, 8000};
    const int lens[3]   = {6400, 1600, 400};

    for (int lvl = 0; lvl < 3; ++lvl) {
        const int L  = lens[lvl];
        const int Lw = L >> 3;                  // 800 / 200 / 50
        const int off = starts[lvl] + w * Lw;

        // ---- Pass 1: per-lane min of squared distance (4-way batched) ----
        float mn = FINF;
        for (int base = 0; base < Lw; base += 128) {
            float cx[4], cy[4];
            #pragma unroll
            for (int j = 0; j < 4; ++j) {
                const int al = base + j * 32 + lane;
                float2 c = make_float2(3.0e18f, 3.0e18f);   // sentinel -> d2 huge
                if (al < Lw) c = g_ac[off + al];
                cx[j] = c.x; cy[j] = c.y;
            }
            #pragma unroll
            for (int j = 0; j < 4; ++j) {
                const float dx = gx - cx[j], dy = gy - cy[j];
                mn = fminf(mn, fmaf(dx, dx, dy * dy));
            }
        }

        // ---- T = 9th smallest of the 32 lane minima, via rank-select ----
        s_min[w][lane] = mn;
        __syncwarp();
        int rank = 0;
        #pragma unroll
        for (int j = 0; j < 32; ++j) {
            const float o = s_min[w][j];
            rank += (o < mn || (o == mn && j < lane)) ? 1 : 0;
        }
        const unsigned rm = __ballot_sync(0xffffffffu, rank == 8);
        const float T = __shfl_sync(0xffffffffu, mn, __ffs(rm) - 1);

        // ---- Pass 2: push slice keys with d2 <= T (rare smem atomics) ----
        if (lane == 0) s_cnt[w] = 0;
        __syncwarp();
        for (int base = 0; base < Lw; base += 128) {
            float cx[4], cy[4];
            #pragma unroll
            for (int j = 0; j < 4; ++j) {
                const int al = base + j * 32 + lane;
                float2 c = make_float2(3.0e18f, 3.0e18f);
                if (al < Lw) c = g_ac[off + al];
                cx[j] = c.x; cy[j] = c.y;
            }
            #pragma unroll
            for (int j = 0; j < 4; ++j) {
                const int al = base + j * 32 + lane;
                const float dx = gx - cx[j], dy = gy - cy[j];
                const float d2 = fmaf(dx, dx, dy * dy);
                if (d2 <= T) {                   // sentinels never qualify
                    const int pos = atomicAdd(&s_cnt[w], 1);
                    if (pos < CAPW)
                        s_buf[w][pos] =
                            ((unsigned long long)__float_as_uint(d2) << 32) |
                            (unsigned int)(off + al);
                }
            }
        }
        __syncwarp();

        // ---- Per-warp rank-select top-9 of C buffered keys ----
        int C = s_cnt[w]; if (C > CAPW) C = CAPW;   // C >= 9 guaranteed
        for (int i = lane; i < C; i += 32) {
            const unsigned long long my = s_buf[w][i];
            int r = 0;
            for (int j = 0; j < C; ++j)
                r += (s_buf[w][j] < my) ? 1 : 0;
            if (r < TOPK)
                s_keys[lvl][w * TOPK + r] = my;
        }
        __syncwarp();                            // s_buf/s_min reused next level
    }
    __syncthreads();

    // Warp 0: rank-select top-9 of each level's 72 keys, then tail.
    if (w == 0) {
        for (int lvl = 0; lvl < 3; ++lvl) {
            #pragma unroll
            for (int half = 0; half < 3; ++half) {
                const int i = lane + half * 32;
                if (i < 72) {
                    const unsigned long long my = s_keys[lvl][i];
                    int r = 0;
                    #pragma unroll
                    for (int j = 0; j < 72; ++j)
                        r += (s_keys[lvl][j] < my) ? 1 : 0;
                    if (r < TOPK)
                        s_cand[lvl * TOPK + r] = (int)(unsigned int)my;
                }
            }
        }
        __syncwarp();

        // Candidate overlaps (_iou2d: unclipped areas, union eps 1e-6)
        float ov = 0.0f;
        int ca = 0;
        float4 ab = make_float4(0.f, 0.f, 0.f, 0.f);
        if (lane < 27) {
            ca = s_cand[lane];
            ab = ((const float4*)anc)[ca];
            const float area1 = (gt.z - gt.x) * (gt.w - gt.y);
            const float area2 = (ab.z - ab.x) * (ab.w - ab.y);
            const float ltx = fmaxf(gt.x, ab.x), lty = fmaxf(gt.y, ab.y);
            const float rbx = fminf(gt.z, ab.z), rby = fminf(gt.w, ab.w);
            const float ww = fmaxf(rbx - ltx, 0.0f), hh = fmaxf(rby - lty, 0.0f);
            const float o = ww * hh;
            ov = o / fmaxf(area1 + area2 - o, 1e-6f);
        }

        // mean + std(ddof=1) threshold via warp sums
        float s = (lane < 27) ? ov : 0.0f;
        #pragma unroll
        for (int sft = 16; sft > 0; sft >>= 1) s += __shfl_xor_sync(0xffffffffu, s, sft);
        const float mean = s * (1.0f / 27.0f);
        float dv = (lane < 27) ? (ov - mean) * (ov - mean) : 0.0f;
        #pragma unroll
        for (int sft = 16; sft > 0; sft >>= 1) dv += __shfl_xor_sync(0xffffffffu, dv, sft);
        const float thr = mean + sqrtf(dv * (1.0f / 26.0f));

        if (lane < 27 && ov > thr) {
            const float ax = (ab.x + ab.z) * 0.5f;
            const float ay = (ab.y + ab.w) * 0.5f;
            const float mn2 = fminf(fminf(ax - gt.x, ay - gt.y),
                                    fminf(gt.z - ax, gt.w - ay));
            if (mn2 > 1e-9f) atomicOr(&g_maskpos[b * NA + ca], 1u << g);
        }
    }
}

// One block per AG=64 anchors. Phase A (64 thr): assignment + small outputs.
// Phase B (256 thr): coalesced score-row writes. (R11-proven version.)
__global__ __launch_bounds__(256) void k_assign(
    const float* __restrict__ anc,
    const int*   __restrict__ gt_labels,
    const float* __restrict__ gtb,
    const float* __restrict__ pd,
    float* __restrict__ o_lab,
    float* __restrict__ o_box,
    float* __restrict__ o_scr,
    float* __restrict__ o_fg)
{
    __shared__ int   s_lab[AG];
    __shared__ float s_scr[AG];

    const int base = blockIdx.x * AG;
    const int tid  = threadIdx.x;

    if (tid < AG) {
        const int idx = base + tid;
        const int b = idx / NA;
        const int a = idx - b * NA;

        const unsigned int m = g_maskpos[idx];
        const int cnt = __popc(m);
        int tgt = 0;
        const bool fg = (cnt > 0);

        if (cnt == 1) {
            tgt = __ffs(m) - 1;
        } else if (cnt > 1) {
            const float4 ab = ((const float4*)anc)[a];
            const float area2 = (ab.z - ab.x) * (ab.w - ab.y);
            float best = -1.0f;
            for (int gg = 0; gg < NM; ++gg) {
                const float4 gb = ((const float4*)gtb)[b * NM + gg];
                const float area1 = (gb.z - gb.x) * (gb.w - gb.y);
                const float ltx = fmaxf(gb.x, ab.x), lty = fmaxf(gb.y, ab.y);
                const float rbx = fminf(gb.z, ab.z), rby = fminf(gb.w, ab.w);
                const float ww = fmaxf(rbx - ltx, 0.0f), hh = fmaxf(rby - lty, 0.0f);
                const float ovv = ww * hh;
                const float v = ovv / fmaxf(area1 + area2 - ovv, 1e-6f);
                if (v > best) { best = v; tgt = gg; }
            }
        }

        const int label = fg ? gt_labels[b * NM + tgt] : NC;
        const float4 tb = ((const float4*)gtb)[b * NM + tgt];

        o_lab[idx] = (float)label;
        ((float4*)o_box)[idx] = tb;
        o_fg[idx] = fg ? 1.0f : 0.0f;

        float score = 0.0f;
        if (fg) {
            const float4 pb = ((const float4*)pd)[(size_t)b * NA + a];
            const float iw = fmaxf(fminf(tb.z, pb.z) - fmaxf(tb.x, pb.x), 0.0f);
            const float ih = fmaxf(fminf(tb.w, pb.w) - fmaxf(tb.y, pb.y), 0.0f);
            const float ovv = iw * ih;
            const float a1 = fmaxf(tb.z - tb.x, 0.0f) * fmaxf(tb.w - tb.y, 0.0f);
            const float a2 = fmaxf(pb.z - pb.x, 0.0f) * fmaxf(pb.w - pb.y, 0.0f);
            score = ovv / (a1 + a2 - ovv + 1e-9f);
        }
        s_lab[tid] = fg ? label : -1;
        s_scr[tid] = score;
    }
    __syncthreads();

    // Phase B: 64 rows x 20 float4 = 1280 float4s, coalesced.
    float4* sc4 = (float4*)o_scr + (size_t)base * (NC / 4);
    #pragma unroll
    for (int it = 0; it < AG * (NC / 4) / 256; ++it) {
        const int j  = it * 256 + tid;
        const int an = j / (NC / 4);
        const int q  = j - an * (NC / 4);
        float4 v = make_float4(0.f, 0.f, 0.f, 0.f);
        const int l = s_lab[an];
        if (l >= 0 && (l >> 2) == q) {
            const float sc = s_scr[an];
            if ((l & 3) == 0) v.x = sc;
            else if ((l & 3) == 1) v.y = sc;
            else if ((l & 3) == 2) v.z = sc;
            else v.w = sc;
        }
        sc4[j] = v;
    }
}

extern "C" void kernel_launch(void* const* d_in, const int* in_sizes, int n_in,
                              void* d_out, int out_size)
{
    const float* anc = (const float*)d_in[0];   // [8400,4]
    const int*   gtl = (const int*)  d_in[1];   // [32,32,1]
    const float* gtb = (const float*)d_in[2];   // [32,32,4]
    const float* mgt = (const float*)d_in[3];   // [32,32,1]
    const float* pd  = (const float*)d_in[4];   // [32,8400,4]

    float* out   = (float*)d_out;
    float* o_lab = out;
    float* o_box = o_lab + (size_t)BSZ * NA;
    float* o_scr = o_box + (size_t)BSZ * NA * 4;
    float* o_fg  = o_scr + (size_t)BSZ * NA * NC;

    k_prep<<<(BSZ * NA / 4 + 255) / 256, 256>>>(anc);
    k_pairs<<<BSZ * NM, 256>>>(anc, gtb, mgt);
    k_assign<<<BSZ * NA / AG, 256>>>(anc, gtl, gtb, pd,
                                     o_lab, o_box, o_scr, o_fg);
}

// round 14
// speedup vs baseline: 1.5919x; 1.5919x over previous
#include <cuda_runtime.h>
#include <cuda_bf16.h>
#include <math.h>

#define NA 8400
#define BSZ 32
#define NM 32
#define NC 80
#define TOPK 9
#define CAPW 64
#define AG 64          // anchors per k_assign block
#define FINF 3.402823e38f

// Padded per-level center layout (each a multiple of 128):
// lvl0: [0,6400) real 0..6399 ; lvl1: [6400,8064) real 6400..7999, pad 64
// lvl2: [8064,8576) real 8000..8399, pad 112
#define P0   6400
#define P1   1664
#define P2   512
#define PO0  0
#define PO1  6400
#define PO2  8064
#define PTOT 8576

__device__ unsigned int g_maskpos[BSZ * NA];
__device__ float2       g_acp[PTOT];            // padded anchor centers

// Zero gt bitmask, fill padded centers (pads = far sentinel).
__global__ __launch_bounds__(256) void k_prep(const float* __restrict__ anc)
{
    const int i = blockIdx.x * blockDim.x + threadIdx.x;
    if (i < BSZ * NA / 4) ((uint4*)g_maskpos)[i] = make_uint4(0u, 0u, 0u, 0u);
    if (i < PTOT) {
        int realIdx = -1;
        if (i < PO1)                 realIdx = i;                     // lvl0
        else if (i < PO2)            { const int li = i - PO1; if (li < 1600) realIdx = 6400 + li; }
        else                         { const int li = i - PO2; if (li < 400)  realIdx = 8000 + li; }
        float2 c = make_float2(3.0e18f, 3.0e18f);
        if (realIdx >= 0) {
            const float4 ab = ((const float4*)anc)[realIdx];
            c = make_float2((ab.x + ab.z) * 0.5f, (ab.y + ab.w) * 0.5f);
        }
        g_acp[i] = c;
    }
}

// One BLOCK (128 thr = 4 warps) per (b,g) pair. Clean padded scan loops.
__global__ __launch_bounds__(128) void k_pairs(
    const float* __restrict__ anc,
    const float* __restrict__ gtb,
    const float* __restrict__ mask_gt)
{
    __shared__ unsigned long long s_keys[3][36];
    __shared__ unsigned long long s_buf[4][CAPW];
    __shared__ float s_min[4][32];
    __shared__ int   s_cnt[4];
    __shared__ int   s_cand[27];

    const int tid  = threadIdx.x;
    const int lane = tid & 31;
    const int wq   = tid >> 5;                  // 0..3

    const int p = blockIdx.x;
    const int b = p >> 5;
    const int g = p & 31;
    if (mask_gt[p] <= 0.0f) return;             // block-uniform -> barriers safe

    const float4 gt = ((const float4*)gtb)[p];
    const float gx = (gt.x + gt.z) * 0.5f;
    const float gy = (gt.y + gt.w) * 0.5f;

    #pragma unroll
    for (int lvl = 0; lvl < 3; ++lvl) {
        const int Lp    = (lvl == 0) ? P0  : (lvl == 1) ? P1  : P2;
        const int ofs   = (lvl == 0) ? PO0 : (lvl == 1) ? PO1 : PO2;
        const int realS = (lvl == 0) ? 0   : (lvl == 1) ? 6400 : 8000;

        // ---- Pass 1: per-lane min of squared distance (no bounds logic) ----
        float mn = FINF;
        #pragma unroll 4
        for (int i = tid; i < Lp; i += 128) {
            const float2 c = g_acp[ofs + i];
            const float dx = gx - c.x, dy = gy - c.y;
            mn = fminf(mn, fmaf(dx, dx, dy * dy));
        }

        // ---- T = 9th smallest of this warp's 32 lane minima (rank-select) ----
        s_min[wq][lane] = mn;
        __syncwarp();
        int rank = 0;
        #pragma unroll
        for (int j = 0; j < 32; ++j) {
            const float o = s_min[wq][j];
            rank += (o < mn || (o == mn && j < lane)) ? 1 : 0;
        }
        const unsigned rm = __ballot_sync(0xffffffffu, rank == 8);
        const float T = __shfl_sync(0xffffffffu, mn, __ffs(rm) - 1);

        // ---- Pass 2: push keys with d2 <= T (pads never qualify) ----
        if (lane == 0) s_cnt[wq] = 0;
        __syncwarp();
        #pragma unroll 4
        for (int i = tid; i < Lp; i += 128) {
            const float2 c = g_acp[ofs + i];
            const float dx = gx - c.x, dy = gy - c.y;
            const float d2 = fmaf(dx, dx, dy * dy);
            if (d2 <= T) {
                const int pos = atomicAdd(&s_cnt[wq], 1);
                if (pos < CAPW)
                    s_buf[wq][pos] =
                        ((unsigned long long)__float_as_uint(d2) << 32) |
                        (unsigned int)(realS + i);
            }
        }
        __syncwarp();

        // ---- Per-warp rank-select top-9 of C buffered keys ----
        int C = s_cnt[wq]; if (C > CAPW) C = CAPW;   // C >= 9 guaranteed
        for (int i = lane; i < C; i += 32) {
            const unsigned long long my = s_buf[wq][i];
            int r = 0;
            for (int j = 0; j < C; ++j)
                r += (s_buf[wq][j] < my) ? 1 : 0;
            if (r < TOPK)
                s_keys[lvl][wq * TOPK + r] = my;
        }
        __syncwarp();                            // s_buf/s_min reused next level
    }
    __syncthreads();

    // Warp 0: rank-select top-9 of each level's 36 keys, then tail.
    if (wq == 0) {
        #pragma unroll
        for (int lvl = 0; lvl < 3; ++lvl) {
            #pragma unroll
            for (int half = 0; half < 2; ++half) {
                const int i = lane + half * 32;
                if (i < 36) {
                    const unsigned long long my = s_keys[lvl][i];
                    int r = 0;
                    #pragma unroll
                    for (int j = 0; j < 36; ++j)
                        r += (s_keys[lvl][j] < my) ? 1 : 0;
                    if (r < TOPK)
                        s_cand[lvl * TOPK + r] = (int)(unsigned int)my;
                }
            }
        }
        __syncwarp();

        // Candidate overlaps (_iou2d: unclipped areas, union eps 1e-6)
        float ov = 0.0f;
        int ca = 0;
        float4 ab = make_float4(0.f, 0.f, 0.f, 0.f);
        if (lane < 27) {
            ca = s_cand[lane];
            ab = ((const float4*)anc)[ca];
            const float area1 = (gt.z - gt.x) * (gt.w - gt.y);
            const float area2 = (ab.z - ab.x) * (ab.w - ab.y);
            const float ltx = fmaxf(gt.x, ab.x), lty = fmaxf(gt.y, ab.y);
            const float rbx = fminf(gt.z, ab.z), rby = fminf(gt.w, ab.w);
            const float ww = fmaxf(rbx - ltx, 0.0f), hh = fmaxf(rby - lty, 0.0f);
            const float o = ww * hh;
            ov = o / fmaxf(area1 + area2 - o, 1e-6f);
        }

        // mean + std(ddof=1) threshold via warp sums
        float s = (lane < 27) ? ov : 0.0f;
        #pragma unroll
        for (int sft = 16; sft > 0; sft >>= 1) s += __shfl_xor_sync(0xffffffffu, s, sft);
        const float mean = s * (1.0f / 27.0f);
        float dv = (lane < 27) ? (ov - mean) * (ov - mean) : 0.0f;
        #pragma unroll
        for (int sft = 16; sft > 0; sft >>= 1) dv += __shfl_xor_sync(0xffffffffu, dv, sft);
        const float thr = mean + sqrtf(dv * (1.0f / 26.0f));

        if (lane < 27 && ov > thr) {
            const float ax = (ab.x + ab.z) * 0.5f;
            const float ay = (ab.y + ab.w) * 0.5f;
            const float mn2 = fminf(fminf(ax - gt.x, ay - gt.y),
                                    fminf(gt.z - ax, gt.w - ay));
            if (mn2 > 1e-9f) atomicOr(&g_maskpos[b * NA + ca], 1u << g);
        }
    }
}

// One block per AG=64 anchors. Phase A (64 thr): assignment + small outputs.
// Phase B (256 thr): coalesced score-row writes. (R11-proven version.)
__global__ __launch_bounds__(256) void k_assign(
    const float* __restrict__ anc,
    const int*   __restrict__ gt_labels,
    const float* __restrict__ gtb,
    const float* __restrict__ pd,
    float* __restrict__ o_lab,
    float* __restrict__ o_box,
    float* __restrict__ o_scr,
    float* __restrict__ o_fg)
{
    __shared__ int   s_lab[AG];
    __shared__ float s_scr[AG];

    const int base = blockIdx.x * AG;
    const int tid  = threadIdx.x;

    if (tid < AG) {
        const int idx = base + tid;
        const int b = idx / NA;
        const int a = idx - b * NA;

        const unsigned int m = g_maskpos[idx];
        const int cnt = __popc(m);
        int tgt = 0;
        const bool fg = (cnt > 0);

        if (cnt == 1) {
            tgt = __ffs(m) - 1;
        } else if (cnt > 1) {
            const float4 ab = ((const float4*)anc)[a];
            const float area2 = (ab.z - ab.x) * (ab.w - ab.y);
            float best = -1.0f;
            for (int gg = 0; gg < NM; ++gg) {
                const float4 gb = ((const float4*)gtb)[b * NM + gg];
                const float area1 = (gb.z - gb.x) * (gb.w - gb.y);
                const float ltx = fmaxf(gb.x, ab.x), lty = fmaxf(gb.y, ab.y);
                const float rbx = fminf(gb.z, ab.z), rby = fminf(gb.w, ab.w);
                const float ww = fmaxf(rbx - ltx, 0.0f), hh = fmaxf(rby - lty, 0.0f);
                const float ovv = ww * hh;
                const float v = ovv / fmaxf(area1 + area2 - ovv, 1e-6f);
                if (v > best) { best = v; tgt = gg; }
            }
        }

        const int label = fg ? gt_labels[b * NM + tgt] : NC;
        const float4 tb = ((const float4*)gtb)[b * NM + tgt];

        o_lab[idx] = (float)label;
        ((float4*)o_box)[idx] = tb;
        o_fg[idx] = fg ? 1.0f : 0.0f;

        float score = 0.0f;
        if (fg) {
            const float4 pb = ((const float4*)pd)[(size_t)b * NA + a];
            const float iw = fmaxf(fminf(tb.z, pb.z) - fmaxf(tb.x, pb.x), 0.0f);
            const float ih = fmaxf(fminf(tb.w, pb.w) - fmaxf(tb.y, pb.y), 0.0f);
            const float ovv = iw * ih;
            const float a1 = fmaxf(tb.z - tb.x, 0.0f) * fmaxf(tb.w - tb.y, 0.0f);
            const float a2 = fmaxf(pb.z - pb.x, 0.0f) * fmaxf(pb.w - pb.y, 0.0f);
            score = ovv / (a1 + a2 - ovv + 1e-9f);
        }
        s_lab[tid] = fg ? label : -1;
        s_scr[tid] = score;
    }
    __syncthreads();

    // Phase B: 64 rows x 20 float4 = 1280 float4s, coalesced.
    float4* sc4 = (float4*)o_scr + (size_t)base * (NC / 4);
    #pragma unroll
    for (int it = 0; it < AG * (NC / 4) / 256; ++it) {
        const int j  = it * 256 + tid;
        const int an = j / (NC / 4);
        const int q  = j - an * (NC / 4);
        float4 v = make_float4(0.f, 0.f, 0.f, 0.f);
        const int l = s_lab[an];
        if (l >= 0 && (l >> 2) == q) {
            const float sc = s_scr[an];
            if ((l & 3) == 0) v.x = sc;
            else if ((l & 3) == 1) v.y = sc;
            else if ((l & 3) == 2) v.z = sc;
            else v.w = sc;
        }
        sc4[j] = v;
    }
}

extern "C" void kernel_launch(void* const* d_in, const int* in_sizes, int n_in,
                              void* d_out, int out_size)
{
    const float* anc = (const float*)d_in[0];   // [8400,4]
    const int*   gtl = (const int*)  d_in[1];   // [32,32,1]
    const float* gtb = (const float*)d_in[2];   // [32,32,4]
    const float* mgt = (const float*)d_in[3];   // [32,32,1]
    const float* pd  = (const float*)d_in[4];   // [32,8400,4]

    float* out   = (float*)d_out;
    float* o_lab = out;
    float* o_box = o_lab + (size_t)BSZ * NA;
    float* o_scr = o_box + (size_t)BSZ * NA * 4;
    float* o_fg  = o_scr + (size_t)BSZ * NA * NC;

    k_prep<<<(BSZ * NA / 4 + 255) / 256, 256>>>(anc);
    k_pairs<<<BSZ * NM, 128>>>(anc, gtb, mgt);
    k_assign<<<BSZ * NA / AG, 256>>>(anc, gtl, gtb, pd,
                                     o_lab, o_box, o_scr, o_fg);
}